// round 2
// baseline (speedup 1.0000x reference)
#include <cuda_runtime.h>

// DotProductCostVolume: out[b,d,h,w] = (1/C) * sum_c left[b,c,h,w]*right[b,c,h,w-d], 0 if w<d
// B=4, C=32, H=256, W=512, D=64, fp32.

#define Bn 4
#define Cn 32
#define Hn 256
#define Wn 512
#define Dn 64
#define TW 128           // output w-columns per CTA
#define RW 192           // TW + 64 halo columns of right
#define NT 128           // threads per CTA

// Element-granular XOR swizzle: makes lane-stride-8 shared reads conflict-free.
__device__ __forceinline__ int sw(int k) { return k ^ ((k >> 5) & 7); }

__global__ __launch_bounds__(NT, 4)
void cost_volume_kernel(const float* __restrict__ left,
                        const float* __restrict__ right,
                        float* __restrict__ out)
{
    __shared__ float Ls[Cn * TW];   // 16 KB
    __shared__ float Rs[Cn * RW];   // 24 KB

    const int tile = blockIdx.x;    // 0..3
    const int h    = blockIdx.y;    // 0..255
    const int b    = blockIdx.z;    // 0..3
    const int w0   = tile * TW;
    const int tid  = threadIdx.x;

    // ---- Stage left tile: L[c][k], k in [0,TW), global w = w0 + k ----
    const float* lbase = left + ((long)(b * Cn) * Hn + h) * Wn;
    #pragma unroll 8
    for (int idx = tid; idx < Cn * TW; idx += NT) {
        int c = idx >> 7;          // /128
        int k = idx & (TW - 1);
        Ls[c * TW + sw(k)] = lbase[c * Hn * Wn + w0 + k];
    }

    // ---- Stage right tile with halo: R[c][k], global w = w0 - 64 + k, zero for w<0 ----
    const float* rbase = right + ((long)(b * Cn) * Hn + h) * Wn;
    #pragma unroll 8
    for (int idx = tid; idx < Cn * RW; idx += NT) {
        int c  = idx / RW;
        int k  = idx - c * RW;
        int gw = w0 - 64 + k;
        float v = (gw >= 0) ? rbase[c * Hn * Wn + gw] : 0.0f;
        Rs[c * RW + sw(k)] = v;
    }
    __syncthreads();

    // ---- Per-thread 8w x 8d register tile ----
    const int wg = tid & 15;   // w-group: covers w0 + wg*8 .. +7
    const int dg = tid >> 4;   // d-group: covers dg*8 .. +7

    float acc[8][8];
    #pragma unroll
    for (int i = 0; i < 8; i++)
        #pragma unroll
        for (int j = 0; j < 8; j++)
            acc[i][j] = 0.0f;

    // Needed R indices per channel: k = 64 + (8wg+i) - (8dg+j), i,j in [0,8)
    //   -> k in [rb, rb+14] with rb = 8wg - 8dg + 57  (>= 1, <= 177; +14 <= 191 < RW)
    const int rb = 8 * wg - 8 * dg + 57;

    // Swizzled offsets are c-invariant: precompute once.
    int loff[8], roff[15];
    #pragma unroll
    for (int i = 0; i < 8; i++)  loff[i] = sw(wg * 8 + i);
    #pragma unroll
    for (int m = 0; m < 15; m++) roff[m] = sw(rb + m);

    #pragma unroll 4
    for (int c = 0; c < Cn; c++) {
        const float* lr = Ls + c * TW;
        const float* rr = Rs + c * RW;
        float l[8], r[15];
        #pragma unroll
        for (int i = 0; i < 8; i++)  l[i] = lr[loff[i]];
        #pragma unroll
        for (int m = 0; m < 15; m++) r[m] = rr[roff[m]];
        #pragma unroll
        for (int i = 0; i < 8; i++)
            #pragma unroll
            for (int j = 0; j < 8; j++)
                acc[i][j] += l[i] * r[7 + i - j];
    }

    // ---- Epilogue: scale by 1/C, vectorized stores ----
    const float sc = 1.0f / (float)Cn;
    float* ob = out + ((long)(b * Dn) * Hn + h) * Wn + w0 + wg * 8;
    #pragma unroll
    for (int j = 0; j < 8; j++) {
        int d = dg * 8 + j;
        float4 v0 = make_float4(acc[0][j] * sc, acc[1][j] * sc,
                                acc[2][j] * sc, acc[3][j] * sc);
        float4 v1 = make_float4(acc[4][j] * sc, acc[5][j] * sc,
                                acc[6][j] * sc, acc[7][j] * sc);
        float4* p = reinterpret_cast<float4*>(ob + (long)d * Hn * Wn);
        p[0] = v0;
        p[1] = v1;
    }
}

extern "C" void kernel_launch(void* const* d_in, const int* in_sizes, int n_in,
                              void* d_out, int out_size)
{
    const float* left  = (const float*)d_in[0];
    const float* right = (const float*)d_in[1];
    float* out = (float*)d_out;

    dim3 grid(Wn / TW, Hn, Bn);   // (4, 256, 4) = 4096 CTAs
    cost_volume_kernel<<<grid, NT>>>(left, right, out);
}

// round 3
// speedup vs baseline: 1.1734x; 1.1734x over previous
#include <cuda_runtime.h>

// DotProductCostVolume: out[b,d,h,w] = (1/C) * sum_c left[b,c,h,w]*right[b,c,h,w-d], 0 if w<d
// B=4, C=32, H=256, W=512, D=64, fp32.
//
// Per CTA: (b, h, 128-wide w-tile). Stage L[32c x 128w] and R[32c x 192w]
// (64-col halo, zero-filled for w<0 so the w<d masking is automatic) in SMEM,
// with a 16B-chunk XOR swizzle so all inner-loop LDS.128 are bank-conflict-free.
// Each thread computes an 8w x 8d register tile: per channel, 2+4 LDS.128
// feed 64 FFMAs.

#define Bn 4
#define Cn 32
#define Hn 256
#define Wn 512
#define Dn 64
#define TW 128           // output w-columns per CTA
#define RW 192           // TW + 64 halo columns of right
#define NT 128           // threads per CTA

#define LCH (TW/4)       // 32 float4 chunks per L row
#define RCH (RW/4)       // 48 float4 chunks per R row

// 16B-chunk XOR swizzle (row-local chunk index q)
__device__ __forceinline__ int swc(int q) { return q ^ ((q >> 3) & 7); }

__global__ __launch_bounds__(NT, 4)
void cost_volume_kernel(const float* __restrict__ left,
                        const float* __restrict__ right,
                        float* __restrict__ out)
{
    __shared__ float4 Ls4[Cn * LCH];   // 16 KB
    __shared__ float4 Rs4[Cn * RCH];   // 24 KB

    const int tile = blockIdx.x;    // 0..3
    const int h    = blockIdx.y;    // 0..255
    const int b    = blockIdx.z;    // 0..3
    const int w0   = tile * TW;
    const int tid  = threadIdx.x;

    const float* lbase = left  + ((long)(b * Cn) * Hn + h) * Wn;
    const float* rbase = right + ((long)(b * Cn) * Hn + h) * Wn;

    // ---- Stage left tile: chunk q of row c holds words [4q, 4q+4) at w0+4q ----
    #pragma unroll 4
    for (int t = tid; t < Cn * LCH; t += NT) {
        int c = t >> 5;             // / 32
        int q = t & (LCH - 1);
        float4 v = *reinterpret_cast<const float4*>(lbase + (long)c * Hn * Wn + w0 + 4 * q);
        Ls4[c * LCH + swc(q)] = v;
    }

    // ---- Stage right tile with halo: chunk q covers global w = w0-64+4q.. ----
    #pragma unroll 4
    for (int t = tid; t < Cn * RCH; t += NT) {
        int c  = t / RCH;
        int q  = t - c * RCH;
        int gw = w0 - 64 + 4 * q;   // chunk is entirely <0 or entirely >=0
        float4 v;
        if (gw >= 0)
            v = *reinterpret_cast<const float4*>(rbase + (long)c * Hn * Wn + gw);
        else
            v = make_float4(0.f, 0.f, 0.f, 0.f);
        Rs4[c * RCH + swc(q)] = v;
    }
    __syncthreads();

    // ---- Per-thread 8w x 8d register tile ----
    const int wg = tid & 15;   // w-group: w0 + 8wg .. +7
    const int dg = tid >> 4;   // d-group: 8dg .. +7

    // L words needed: 8wg..8wg+7 -> chunks 2wg, 2wg+1
    const float4* La = &Ls4[swc(2 * wg)];
    const float4* Lb = &Ls4[swc(2 * wg + 1)];

    // R words needed: rv[n] = word 8(wg-dg)+56 + n, n in [1,15]
    // base word 8(wg-dg)+56 is 4-aligned -> chunks q0..q0+3, q0 = 2(wg-dg)+14 in [0,44]
    const int q0 = 2 * (wg - dg) + 14;
    const float4* R0 = &Rs4[swc(q0 + 0)];
    const float4* R1 = &Rs4[swc(q0 + 1)];
    const float4* R2 = &Rs4[swc(q0 + 2)];
    const float4* R3 = &Rs4[swc(q0 + 3)];

    float acc[8][8];
    #pragma unroll
    for (int i = 0; i < 8; i++)
        #pragma unroll
        for (int j = 0; j < 8; j++)
            acc[i][j] = 0.0f;

    #pragma unroll
    for (int c = 0; c < Cn; c++) {
        float4 la = La[c * LCH];
        float4 lb = Lb[c * LCH];
        float4 ra = R0[c * RCH];
        float4 rb = R1[c * RCH];
        float4 rc = R2[c * RCH];
        float4 rd = R3[c * RCH];

        float l[8]  = { la.x, la.y, la.z, la.w, lb.x, lb.y, lb.z, lb.w };
        float rv[16] = { ra.x, ra.y, ra.z, ra.w,
                         rb.x, rb.y, rb.z, rb.w,
                         rc.x, rc.y, rc.z, rc.w,
                         rd.x, rd.y, rd.z, rd.w };

        #pragma unroll
        for (int i = 0; i < 8; i++)
            #pragma unroll
            for (int j = 0; j < 8; j++)
                acc[i][j] += l[i] * rv[8 + i - j];   // n = 8+i-j in [1,15]
    }

    // ---- Epilogue: scale by 1/C, vectorized stores ----
    const float sc = 1.0f / (float)Cn;
    float* ob = out + ((long)(b * Dn) * Hn + h) * Wn + w0 + wg * 8;
    #pragma unroll
    for (int j = 0; j < 8; j++) {
        int d = dg * 8 + j;
        float4 v0 = make_float4(acc[0][j] * sc, acc[1][j] * sc,
                                acc[2][j] * sc, acc[3][j] * sc);
        float4 v1 = make_float4(acc[4][j] * sc, acc[5][j] * sc,
                                acc[6][j] * sc, acc[7][j] * sc);
        float4* p = reinterpret_cast<float4*>(ob + (long)d * Hn * Wn);
        p[0] = v0;
        p[1] = v1;
    }
}

extern "C" void kernel_launch(void* const* d_in, const int* in_sizes, int n_in,
                              void* d_out, int out_size)
{
    const float* left  = (const float*)d_in[0];
    const float* right = (const float*)d_in[1];
    float* out = (float*)d_out;

    dim3 grid(Wn / TW, Hn, Bn);   // (4, 256, 4) = 4096 CTAs
    cost_volume_kernel<<<grid, NT>>>(left, right, out);
}